// round 4
// baseline (speedup 1.0000x reference)
#include <cuda_runtime.h>
#include <cuda_bf16.h>

// Problem: B=8, S=512, D=512, MAX_LEN=512, fp32.
// scores[b,i,k] = sum_d Q[b,i,d]*K[b,k,d]  +  sum_m P[b,i,m]*E[m,k]
// P[b,i,m] = Q[b,i,i-m] (1<=m<=i), P[b,i,0] = Q[b,i,i] + sum_{j>i} Q[b,i,j], else 0.
// => one batched fp32 GEMM with effective K=1024 (two 512 phases).

#define BATCH 8
#define SEQ   512
#define DM    512

__device__ float g_P[BATCH * SEQ * DM];   // 8.4 MB scratch (allocation-free)

// ---------------------------------------------------------------------------
// Kernel 1: build P. One block per (b, i) row.
// ---------------------------------------------------------------------------
__global__ __launch_bounds__(256) void build_P_kernel(const float* __restrict__ q) {
    const int i = blockIdx.x;
    const int b = blockIdx.y;
    const float* qr = q + ((size_t)(b * SEQ + i)) * DM;
    float* Pr = g_P + ((size_t)(b * SEQ + i)) * DM;

    __shared__ float sq[DM];
    __shared__ float red[256];

    const int t = threadIdx.x;
    float v0 = qr[t];
    float v1 = qr[t + 256];
    sq[t] = v0;
    sq[t + 256] = v1;

    float s = 0.f;
    if (t > i)       s += v0;
    if (t + 256 > i) s += v1;
    red[t] = s;
    __syncthreads();
#pragma unroll
    for (int off = 128; off > 0; off >>= 1) {
        if (t < off) red[t] += red[t + off];
        __syncthreads();
    }
    const float tail = red[0];

#pragma unroll
    for (int h = 0; h < 2; ++h) {
        int m = t + h * 256;
        float val = (m <= i) ? sq[i - m] : 0.f;
        if (m == 0) val += tail;
        Pr[m] = val;
    }
}

// ---------------------------------------------------------------------------
// Kernel 2: fused batched GEMM, packed f32x2 math.
//   out[b] = Q[b] @ K[b]^T + P[b] @ E
// Tile 128(M) x 64(N), 256 threads, per-thread 8 rows x 4 cols (2 col-pairs).
// A stored ROW-DUPLICATED in smem so row-splats are direct broadcast LDS.128;
// B float4 gives natural col-pairs. 16 fma.rn.f32x2 + 5 LDS.128 per kk.
// K-chunk 8; chunks 0..63 = phase 0 (Q,K^T), 64..127 = phase 1 (P,E).
// ---------------------------------------------------------------------------

#define FMA2(d, a, bb) asm("fma.rn.f32x2 %0, %1, %2, %0;" : "+l"(d) : "l"(a), "l"(bb))

__device__ __forceinline__ unsigned long long dup2(float v) {
    unsigned u = __float_as_uint(v);
    return ((unsigned long long)u << 32) | u;
}
__device__ __forceinline__ float lo32(unsigned long long v) {
    return __uint_as_float((unsigned)(v & 0xffffffffull));
}
__device__ __forceinline__ float hi32(unsigned long long v) {
    return __uint_as_float((unsigned)(v >> 32));
}

struct __align__(16) ULL2 { unsigned long long lo, hi; };

__global__ __launch_bounds__(256, 2) void fused_gemm_kernel(
    const float* __restrict__ Q, const float* __restrict__ K,
    const float* __restrict__ E, float* __restrict__ out)
{
    // A duplicated: As2[kk][2*row] == As2[kk][2*row+1] == A[row][kk].
    // Row stride 260 floats (pad) keeps STS.64 bank spread and 16B alignment.
    __shared__ float As2[8][260];
    __shared__ float Bs[8][64];

    const int b    = blockIdx.z;
    const int row0 = blockIdx.y * 128;
    const int col0 = blockIdx.x * 64;

    const float* Qb = Q   + (size_t)b * SEQ * DM;
    const float* Kb = K   + (size_t)b * SEQ * DM;
    const float* Pb = g_P + (size_t)b * SEQ * DM;

    const int tid = threadIdx.x;
    const int tx  = tid & 15;   // col group: cols col0 + tx*4 + {0..3}
    const int ty  = tid >> 4;   // row group: rows row0 + ty*4 + {0..3, 64..67}

    unsigned long long acc[8][2];
#pragma unroll
    for (int r = 0; r < 8; ++r) { acc[r][0] = 0ull; acc[r][1] = 0ull; }

    // A loading: 128 rows x 8 k; 256 threads x float4 (one row, 4 k-values).
    const int a_row = tid >> 1;         // 0..127
    const int a_c4  = (tid & 1) << 2;   // 0 or 4
    // B phase 0 (K^T): 64 rows x 8 k; threads 0..127 x float4.
    const int b_row = (tid & 127) >> 1;        // 0..63
    const int b_c4  = (tid & 1) << 2;
    // B phase 1 (E): 8 rows x 64 cols; threads 0..127 x float4.
    const int e_row = (tid & 127) >> 4;        // 0..7
    const int e_c4  = (tid & 15) << 2;         // 0..60
    const bool bldr = tid < 128;

    const int NCHUNK = 128;

    // --- prefetch chunk 0 ---
    float4 av = *(const float4*)(Qb + (size_t)(row0 + a_row) * DM + a_c4);
    float4 bv = make_float4(0.f, 0.f, 0.f, 0.f);
    if (bldr) bv = *(const float4*)(Kb + (size_t)(col0 + b_row) * DM + b_c4);

    for (int ks = 0; ks < NCHUNK; ++ks) {
        const int phase = ks >> 6;

        __syncthreads();   // previous chunk fully consumed
        // Store A duplicated (4 x STS.64 of (v,v)).
        *(unsigned long long*)&As2[a_c4 + 0][2 * a_row] = dup2(av.x);
        *(unsigned long long*)&As2[a_c4 + 1][2 * a_row] = dup2(av.y);
        *(unsigned long long*)&As2[a_c4 + 2][2 * a_row] = dup2(av.z);
        *(unsigned long long*)&As2[a_c4 + 3][2 * a_row] = dup2(av.w);
        if (bldr) {
            if (phase == 0) {
                Bs[b_c4 + 0][b_row] = bv.x;
                Bs[b_c4 + 1][b_row] = bv.y;
                Bs[b_c4 + 2][b_row] = bv.z;
                Bs[b_c4 + 3][b_row] = bv.w;
            } else {
                *(float4*)&Bs[e_row][e_c4] = bv;
            }
        }
        __syncthreads();

        // --- prefetch chunk ks+1 (covered by this chunk's compute) ---
        float4 av_n, bv_n;
        if (ks + 1 < NCHUNK) {
            const int ksn    = ks + 1;
            const int phasen = ksn >> 6;
            const int k0n    = (ksn & 63) * 8;
            const float* An  = phasen ? Pb : Qb;
            av_n = *(const float4*)(An + (size_t)(row0 + a_row) * DM + k0n + a_c4);
            if (bldr) {
                if (phasen == 0) {
                    bv_n = *(const float4*)(Kb + (size_t)(col0 + b_row) * DM + k0n + b_c4);
                } else {
                    bv_n = *(const float4*)(E + (size_t)(k0n + e_row) * DM + col0 + e_c4);
                }
            }
        }

#pragma unroll
        for (int kk = 0; kk < 8; ++kk) {
            // Row splats: duplicated pairs, broadcast LDS.128 (addr depends on ty only).
            ULL2 A01 = *(const ULL2*)&As2[kk][ty * 8];
            ULL2 A23 = *(const ULL2*)&As2[kk][ty * 8 + 4];
            ULL2 A45 = *(const ULL2*)&As2[kk][ty * 8 + 128];
            ULL2 A67 = *(const ULL2*)&As2[kk][ty * 8 + 132];
            // Col pairs: natural packing of B float4.
            ULL2 Bp  = *(const ULL2*)&Bs[kk][tx * 4];

            FMA2(acc[0][0], A01.lo, Bp.lo); FMA2(acc[0][1], A01.lo, Bp.hi);
            FMA2(acc[1][0], A01.hi, Bp.lo); FMA2(acc[1][1], A01.hi, Bp.hi);
            FMA2(acc[2][0], A23.lo, Bp.lo); FMA2(acc[2][1], A23.lo, Bp.hi);
            FMA2(acc[3][0], A23.hi, Bp.lo); FMA2(acc[3][1], A23.hi, Bp.hi);
            FMA2(acc[4][0], A45.lo, Bp.lo); FMA2(acc[4][1], A45.lo, Bp.hi);
            FMA2(acc[5][0], A45.hi, Bp.lo); FMA2(acc[5][1], A45.hi, Bp.hi);
            FMA2(acc[6][0], A67.lo, Bp.lo); FMA2(acc[6][1], A67.lo, Bp.hi);
            FMA2(acc[7][0], A67.hi, Bp.lo); FMA2(acc[7][1], A67.hi, Bp.hi);
        }

        av = av_n;
        bv = bv_n;
    }

    // Epilogue: rows row0 + ty*4 + {0..3} and +64; cols col0 + tx*4 + {0..3}.
    float* ob = out + (size_t)b * SEQ * SEQ;
#pragma unroll
    for (int r = 0; r < 8; ++r) {
        int row = row0 + ty * 4 + ((r < 4) ? r : (60 + r));
        float4 v = make_float4(lo32(acc[r][0]), hi32(acc[r][0]),
                               lo32(acc[r][1]), hi32(acc[r][1]));
        *(float4*)(ob + (size_t)row * SEQ + col0 + tx * 4) = v;
    }
}

// ---------------------------------------------------------------------------
extern "C" void kernel_launch(void* const* d_in, const int* in_sizes, int n_in,
                              void* d_out, int out_size) {
    const float* q = (const float*)d_in[0];
    const float* k = (const float*)d_in[1];
    const float* e = (const float*)d_in[2];
    float* out = (float*)d_out;

    (void)in_sizes; (void)n_in; (void)out_size;

    build_P_kernel<<<dim3(SEQ, BATCH), 256>>>(q);
    fused_gemm_kernel<<<dim3(SEQ / 64, SEQ / 128, BATCH), 256>>>(q, k, e, out);
}

// round 9
// speedup vs baseline: 2.3407x; 2.3407x over previous
#include <cuda_runtime.h>
#include <cuda_bf16.h>
#include <cstdint>

// Problem: B=8, S=512, D=512, MAX_LEN=512, fp32 in/out.
// scores[b,i,n] = sum_d Q[b,i,d]*K[b,n,d] + sum_m P[b,i,m]*E[m,n]
// P[b,i,m] = Q[b,i,i-m] (1<=m<=i), P[b,i,0] = Q[b,i,i] + sum_{j>i} Q[b,i,j], else 0.
// Strategy: bf16x3 via warp-level HMMA (mma.sync m16n8k16), fp32 accum.
// (tcgen05 is unavailable: harness compiles for plain sm_100, no 'a' features.)

#define BATCH 8
#define SEQ   512
#define DM    512
#define NELEM (BATCH * SEQ * DM)

__device__ __nv_bfloat16 g_Qh[NELEM], g_Ql[NELEM];
__device__ __nv_bfloat16 g_Kh[NELEM], g_Kl[NELEM];
__device__ __nv_bfloat16 g_Ph[NELEM], g_Pl[NELEM];
__device__ __nv_bfloat16 g_Eth[SEQ * DM], g_Etl[SEQ * DM];  // Et[n][m] = E[m][n]

__device__ __forceinline__ void split_bf16(float x, __nv_bfloat16& h, __nv_bfloat16& l) {
    h = __float2bfloat16(x);
    l = __float2bfloat16(x - __bfloat162float(h));
}
__device__ __forceinline__ uint32_t smem_u32(const void* p) {
    uint32_t a;
    asm("{ .reg .u64 t; cvta.to.shared.u64 t, %1; cvt.u32.u64 %0, t; }" : "=r"(a) : "l"(p));
    return a;
}

// ---------------------------------------------------------------------------
// Kernel 1: build P, store as bf16 hi/lo. One block per (b,i) row.
// ---------------------------------------------------------------------------
__global__ __launch_bounds__(256) void build_P_kernel(const float* __restrict__ q) {
    const int i = blockIdx.x;
    const int b = blockIdx.y;
    const size_t rb = ((size_t)(b * SEQ + i)) * DM;
    const float* qr = q + rb;

    __shared__ float sq[DM];
    __shared__ float red[256];

    const int t = threadIdx.x;
    float v0 = qr[t];
    float v1 = qr[t + 256];
    sq[t] = v0;
    sq[t + 256] = v1;

    float s = 0.f;
    if (t > i)       s += v0;
    if (t + 256 > i) s += v1;
    red[t] = s;
    __syncthreads();
#pragma unroll
    for (int off = 128; off > 0; off >>= 1) {
        if (t < off) red[t] += red[t + off];
        __syncthreads();
    }
    const float tail = red[0];

#pragma unroll
    for (int h = 0; h < 2; ++h) {
        int m = t + h * 256;
        float val = (m <= i) ? sq[i - m] : 0.f;
        if (m == 0) val += tail;
        __nv_bfloat16 hv, lv;
        split_bf16(val, hv, lv);
        g_Ph[rb + m] = hv;
        g_Pl[rb + m] = lv;
    }
}

// ---------------------------------------------------------------------------
// Kernel 2: decompose Q and K (blockIdx.y selects). 8 elems/thread.
// ---------------------------------------------------------------------------
__global__ __launch_bounds__(256) void dec_qk_kernel(const float* __restrict__ q,
                                                     const float* __restrict__ k) {
    const size_t idx = ((size_t)blockIdx.x * 256 + threadIdx.x) * 8;
    const float* src = blockIdx.y ? k : q;
    __nv_bfloat16* dh = blockIdx.y ? g_Kh : g_Qh;
    __nv_bfloat16* dl = blockIdx.y ? g_Kl : g_Ql;

    float4 x0 = *(const float4*)(src + idx);
    float4 x1 = *(const float4*)(src + idx + 4);
    float xs[8] = {x0.x, x0.y, x0.z, x0.w, x1.x, x1.y, x1.z, x1.w};

    unsigned uh[4], ul[4];
#pragma unroll
    for (int i = 0; i < 4; ++i) {
        __nv_bfloat16 ha, la, hb, lb;
        split_bf16(xs[2 * i],     ha, la);
        split_bf16(xs[2 * i + 1], hb, lb);
        uh[i] = ((unsigned)__bfloat16_as_ushort(hb) << 16) | __bfloat16_as_ushort(ha);
        ul[i] = ((unsigned)__bfloat16_as_ushort(lb) << 16) | __bfloat16_as_ushort(la);
    }
    *(uint4*)(dh + idx) = make_uint4(uh[0], uh[1], uh[2], uh[3]);
    *(uint4*)(dl + idx) = make_uint4(ul[0], ul[1], ul[2], ul[3]);
}

// ---------------------------------------------------------------------------
// Kernel 3: transpose + decompose E. Et[n][m] = E[m][n]. 32x32 tiles.
// ---------------------------------------------------------------------------
__global__ __launch_bounds__(256) void dec_E_kernel(const float* __restrict__ E) {
    __shared__ float tile[32][33];
    const int n0 = blockIdx.x * 32;
    const int m0 = blockIdx.y * 32;
    const int tx = threadIdx.x & 31;
    const int ty = threadIdx.x >> 5;

#pragma unroll
    for (int j = 0; j < 4; ++j) {
        int m = ty * 4 + j;
        tile[m][tx] = E[(size_t)(m0 + m) * DM + n0 + tx];
    }
    __syncthreads();
#pragma unroll
    for (int j = 0; j < 4; ++j) {
        int n = ty * 4 + j;
        float v = tile[tx][n];
        __nv_bfloat16 hv, lv;
        split_bf16(v, hv, lv);
        size_t o = (size_t)(n0 + n) * DM + m0 + tx;
        g_Eth[o] = hv;
        g_Etl[o] = lv;
    }
}

// ---------------------------------------------------------------------------
// Kernel 4: HMMA GEMM. 128x128 tile/CTA, grid 4x4x8 = 128 CTAs (1 wave).
// 8 warps, each 64x32 (wy = wid&1 row-half, wx = wid>>1 col-quarter).
// K-chunks of 32: 2 phases x 16 chunks. Per chunk: 4 tiles (Ah,Al,Bh,Bl)
// via cp.async (double buffered), 3 products (AhBh, AhBl, AlBh) accumulated.
// ---------------------------------------------------------------------------
#define BK        32
#define STRIDE    40                       // bf16 elems per smem row (pad 8)
#define ROW_B     (STRIDE * 2)             // 80 bytes, 16B-aligned
#define TILE_B    (128 * ROW_B)            // 10240
#define STAGE_B   (4 * TILE_B)             // 40960
#define GEMM_SMEM (2 * STAGE_B)            // 81920

#define MMA_BF16(c, a, b) \
    asm volatile("mma.sync.aligned.m16n8k16.row.col.f32.bf16.bf16.f32 " \
        "{%0,%1,%2,%3}, {%4,%5,%6,%7}, {%8,%9}, {%0,%1,%2,%3};" \
        : "+f"((c)[0]), "+f"((c)[1]), "+f"((c)[2]), "+f"((c)[3]) \
        : "r"((a)[0]), "r"((a)[1]), "r"((a)[2]), "r"((a)[3]), "r"((b)[0]), "r"((b)[1]))

#define LDSM_X4(r, addr) \
    asm volatile("ldmatrix.sync.aligned.m8n8.x4.shared.b16 {%0,%1,%2,%3}, [%4];" \
        : "=r"((r)[0]), "=r"((r)[1]), "=r"((r)[2]), "=r"((r)[3]) : "r"(addr))

#define LDSM_X2(r, addr) \
    asm volatile("ldmatrix.sync.aligned.m8n8.x2.shared.b16 {%0,%1}, [%2];" \
        : "=r"((r)[0]), "=r"((r)[1]) : "r"(addr))

#define CP_ASYNC16(dst, src) \
    asm volatile("cp.async.cg.shared.global [%0], [%1], 16;" :: "r"(dst), "l"(src))

struct StagePtrs { const __nv_bfloat16 *Ah, *Al, *Bh, *Bl; };

__device__ __forceinline__ StagePtrs stage_ptrs(int s, int b, int row0, int col0) {
    const int phase = s >> 4;
    const int kofs  = (s & 15) * BK;
    StagePtrs sp;
    if (phase == 0) {
        sp.Ah = g_Qh + ((size_t)b * SEQ + row0) * DM + kofs;
        sp.Al = g_Ql + ((size_t)b * SEQ + row0) * DM + kofs;
        sp.Bh = g_Kh + ((size_t)b * SEQ + col0) * DM + kofs;
        sp.Bl = g_Kl + ((size_t)b * SEQ + col0) * DM + kofs;
    } else {
        sp.Ah = g_Ph + ((size_t)b * SEQ + row0) * DM + kofs;
        sp.Al = g_Pl + ((size_t)b * SEQ + row0) * DM + kofs;
        sp.Bh = g_Eth + (size_t)col0 * DM + kofs;
        sp.Bl = g_Etl + (size_t)col0 * DM + kofs;
    }
    return sp;
}

__global__ __launch_bounds__(256, 1) void mma_gemm_kernel(float* __restrict__ out) {
    extern __shared__ char smem[];
    const uint32_t sb = smem_u32(smem);

    const int tid = threadIdx.x;
    const int wid = tid >> 5;
    const int lid = tid & 31;
    const int wy  = wid & 1;       // row half (0..1) -> 64 rows
    const int wx  = wid >> 1;      // col quarter (0..3) -> 32 cols
    const int b    = blockIdx.z;
    const int row0 = blockIdx.y * 128;
    const int col0 = blockIdx.x * 128;

    // cp.async mapping: thread t -> row t>>1, 16-col half (t&1); 2 chunks of 8.
    const int l_row = tid >> 1;
    const int l_c16 = (tid & 1) * 16;
    const uint32_t st_off = (uint32_t)(l_row * ROW_B + l_c16 * 2);

    float acc[4][4][4];
#pragma unroll
    for (int mt = 0; mt < 4; ++mt)
#pragma unroll
        for (int nt = 0; nt < 4; ++nt)
#pragma unroll
            for (int r = 0; r < 4; ++r) acc[mt][nt][r] = 0.f;

    // ldmatrix base offsets (within a tile) for this lane.
    const uint32_t a_lm = (uint32_t)((wy * 64 + (lid & 15)) * ROW_B + (lid >> 4) * 16);
    const uint32_t b_lm = (uint32_t)((wx * 32 + (lid & 7)) * ROW_B + ((lid >> 3) & 1) * 16);

    const int NCHUNK = 32;

    // Prologue: stage 0.
    {
        StagePtrs sp = stage_ptrs(0, b, row0, col0);
        const size_t go = (size_t)l_row * DM + l_c16;
        uint32_t d = sb + st_off;
        CP_ASYNC16(d,                       sp.Ah + go);
        CP_ASYNC16(d + 16,                  sp.Ah + go + 8);
        CP_ASYNC16(d + TILE_B,              sp.Al + go);
        CP_ASYNC16(d + TILE_B + 16,         sp.Al + go + 8);
        CP_ASYNC16(d + 2 * TILE_B,          sp.Bh + go);
        CP_ASYNC16(d + 2 * TILE_B + 16,     sp.Bh + go + 8);
        CP_ASYNC16(d + 3 * TILE_B,          sp.Bl + go);
        CP_ASYNC16(d + 3 * TILE_B + 16,     sp.Bl + go + 8);
        asm volatile("cp.async.commit_group;");
    }

    for (int s = 0; s < NCHUNK; ++s) {
        // Issue stage s+1, then wait for stage s.
        if (s + 1 < NCHUNK) {
            StagePtrs sp = stage_ptrs(s + 1, b, row0, col0);
            const size_t go = (size_t)l_row * DM + l_c16;
            uint32_t d = sb + ((s + 1) & 1) * STAGE_B + st_off;
            CP_ASYNC16(d,                   sp.Ah + go);
            CP_ASYNC16(d + 16,              sp.Ah + go + 8);
            CP_ASYNC16(d + TILE_B,          sp.Al + go);
            CP_ASYNC16(d + TILE_B + 16,     sp.Al + go + 8);
            CP_ASYNC16(d + 2 * TILE_B,      sp.Bh + go);
            CP_ASYNC16(d + 2 * TILE_B + 16, sp.Bh + go + 8);
            CP_ASYNC16(d + 3 * TILE_B,      sp.Bl + go);
            CP_ASYNC16(d + 3 * TILE_B + 16, sp.Bl + go + 8);
            asm volatile("cp.async.commit_group;");
            asm volatile("cp.async.wait_group 1;");
        } else {
            asm volatile("cp.async.wait_group 0;");
        }
        __syncthreads();

        const uint32_t base = sb + (s & 1) * STAGE_B;
        const uint32_t tAh = base, tAl = base + TILE_B;
        const uint32_t tBh = base + 2 * TILE_B, tBl = base + 3 * TILE_B;

#pragma unroll
        for (int ks = 0; ks < 2; ++ks) {
            const uint32_t kb = ks * 32;   // 16 bf16 = 32 bytes
            uint32_t ah[4][4], al[4][4], bh[4][2], bl[4][2];
#pragma unroll
            for (int mt = 0; mt < 4; ++mt) {
                LDSM_X4(ah[mt], tAh + a_lm + mt * 16 * ROW_B + kb);
                LDSM_X4(al[mt], tAl + a_lm + mt * 16 * ROW_B + kb);
            }
#pragma unroll
            for (int nt = 0; nt < 4; ++nt) {
                LDSM_X2(bh[nt], tBh + b_lm + nt * 8 * ROW_B + kb);
                LDSM_X2(bl[nt], tBl + b_lm + nt * 8 * ROW_B + kb);
            }
#pragma unroll
            for (int mt = 0; mt < 4; ++mt)
#pragma unroll
                for (int nt = 0; nt < 4; ++nt) {
                    MMA_BF16(acc[mt][nt], ah[mt], bh[nt]);
                    MMA_BF16(acc[mt][nt], ah[mt], bl[nt]);
                    MMA_BF16(acc[mt][nt], al[mt], bh[nt]);
                }
        }
        __syncthreads();
    }

    // Epilogue: m16n8 layout -> rows (lid>>2)+{0,8}, cols (lid&3)*2+{0,1}.
    float* ob = out + (size_t)b * SEQ * SEQ;
#pragma unroll
    for (int mt = 0; mt < 4; ++mt) {
#pragma unroll
        for (int nt = 0; nt < 4; ++nt) {
            const int rbase = row0 + wy * 64 + mt * 16 + (lid >> 2);
            const int c     = col0 + wx * 32 + nt * 8 + (lid & 3) * 2;
            *(float2*)(ob + (size_t)rbase * SEQ + c) =
                make_float2(acc[mt][nt][0], acc[mt][nt][1]);
            *(float2*)(ob + (size_t)(rbase + 8) * SEQ + c) =
                make_float2(acc[mt][nt][2], acc[mt][nt][3]);
        }
    }
}

// ---------------------------------------------------------------------------
extern "C" void kernel_launch(void* const* d_in, const int* in_sizes, int n_in,
                              void* d_out, int out_size) {
    const float* q = (const float*)d_in[0];
    const float* k = (const float*)d_in[1];
    const float* e = (const float*)d_in[2];
    float* out = (float*)d_out;
    (void)in_sizes; (void)n_in; (void)out_size;

    build_P_kernel<<<dim3(SEQ, BATCH), 256>>>(q);
    dec_qk_kernel<<<dim3(NELEM / 8 / 256, 2), 256>>>(q, k);
    dec_E_kernel<<<dim3(16, 16), 256>>>(e);

    cudaFuncSetAttribute(mma_gemm_kernel,
                         cudaFuncAttributeMaxDynamicSharedMemorySize, GEMM_SMEM);
    mma_gemm_kernel<<<dim3(4, 4, BATCH), 256, GEMM_SMEM>>>(out);
}

// round 11
// speedup vs baseline: 2.8336x; 1.2106x over previous
#include <cuda_runtime.h>
#include <cuda_bf16.h>
#include <cstdint>

// Problem: B=8, S=512, D=512, MAX_LEN=512, fp32 in/out.
// scores[b,i,n] = sum_d Q[b,i,d]*K[b,n,d] + sum_m P[b,i,m]*E[m,n]
// P[b,i,m] = Q[b,i,i-m] (1<=m<=i), P[b,i,0] = Q[b,i,i] + sum_{j>i} Q[b,i,j], else 0.
// Strategy: bf16x3 via warp-level HMMA (mma.sync m16n8k16), fp32 accum.

#define BATCH 8
#define SEQ   512
#define DM    512
#define NELEM (BATCH * SEQ * DM)

__device__ __nv_bfloat16 g_Qh[NELEM], g_Ql[NELEM];
__device__ __nv_bfloat16 g_Kh[NELEM], g_Kl[NELEM];
__device__ __nv_bfloat16 g_Ph[NELEM], g_Pl[NELEM];
__device__ __nv_bfloat16 g_Eth[SEQ * DM], g_Etl[SEQ * DM];  // Et[n][m] = E[m][n]

__device__ __forceinline__ void split_bf16(float x, __nv_bfloat16& h, __nv_bfloat16& l) {
    h = __float2bfloat16(x);
    l = __float2bfloat16(x - __bfloat162float(h));
}
__device__ __forceinline__ uint32_t smem_u32(const void* p) {
    uint32_t a;
    asm("{ .reg .u64 t; cvta.to.shared.u64 t, %1; cvt.u32.u64 %0, t; }" : "=r"(a) : "l"(p));
    return a;
}

// ---------------------------------------------------------------------------
// Kernel 1: build P (bf16 hi/lo) AND decompose Q (row already in smem).
// ---------------------------------------------------------------------------
__global__ __launch_bounds__(256) void build_P_kernel(const float* __restrict__ q) {
    const int i = blockIdx.x;
    const int b = blockIdx.y;
    const size_t rb = ((size_t)(b * SEQ + i)) * DM;
    const float* qr = q + rb;

    __shared__ float sq[DM];
    __shared__ float red[256];

    const int t = threadIdx.x;
    float v0 = qr[t];
    float v1 = qr[t + 256];
    sq[t] = v0;
    sq[t + 256] = v1;

    // Q decomposition (free: values already in registers)
    {
        __nv_bfloat16 h0, l0, h1, l1;
        split_bf16(v0, h0, l0);
        split_bf16(v1, h1, l1);
        g_Qh[rb + t] = h0;       g_Ql[rb + t] = l0;
        g_Qh[rb + t + 256] = h1; g_Ql[rb + t + 256] = l1;
    }

    float s = 0.f;
    if (t > i)       s += v0;
    if (t + 256 > i) s += v1;
    red[t] = s;
    __syncthreads();
#pragma unroll
    for (int off = 128; off > 0; off >>= 1) {
        if (t < off) red[t] += red[t + off];
        __syncthreads();
    }
    const float tail = red[0];

#pragma unroll
    for (int h = 0; h < 2; ++h) {
        int m = t + h * 256;
        float val = (m <= i) ? sq[i - m] : 0.f;
        if (m == 0) val += tail;
        __nv_bfloat16 hv, lv;
        split_bf16(val, hv, lv);
        g_Ph[rb + m] = hv;
        g_Pl[rb + m] = lv;
    }
}

// ---------------------------------------------------------------------------
// Kernel 2: decompose K. 8 elems/thread.
// ---------------------------------------------------------------------------
__global__ __launch_bounds__(256) void dec_k_kernel(const float* __restrict__ k) {
    const size_t idx = ((size_t)blockIdx.x * 256 + threadIdx.x) * 8;

    float4 x0 = *(const float4*)(k + idx);
    float4 x1 = *(const float4*)(k + idx + 4);
    float xs[8] = {x0.x, x0.y, x0.z, x0.w, x1.x, x1.y, x1.z, x1.w};

    unsigned uh[4], ul[4];
#pragma unroll
    for (int i = 0; i < 4; ++i) {
        __nv_bfloat16 ha, la, hb, lb;
        split_bf16(xs[2 * i],     ha, la);
        split_bf16(xs[2 * i + 1], hb, lb);
        uh[i] = ((unsigned)__bfloat16_as_ushort(hb) << 16) | __bfloat16_as_ushort(ha);
        ul[i] = ((unsigned)__bfloat16_as_ushort(lb) << 16) | __bfloat16_as_ushort(la);
    }
    *(uint4*)(g_Kh + idx) = make_uint4(uh[0], uh[1], uh[2], uh[3]);
    *(uint4*)(g_Kl + idx) = make_uint4(ul[0], ul[1], ul[2], ul[3]);
}

// ---------------------------------------------------------------------------
// Kernel 3: transpose + decompose E. Et[n][m] = E[m][n]. 32x32 tiles.
// ---------------------------------------------------------------------------
__global__ __launch_bounds__(256) void dec_E_kernel(const float* __restrict__ E) {
    __shared__ float tile[32][33];
    const int n0 = blockIdx.x * 32;
    const int m0 = blockIdx.y * 32;
    const int tx = threadIdx.x & 31;
    const int ty = threadIdx.x >> 5;

#pragma unroll
    for (int j = 0; j < 4; ++j) {
        int m = ty * 4 + j;
        tile[m][tx] = E[(size_t)(m0 + m) * DM + n0 + tx];
    }
    __syncthreads();
#pragma unroll
    for (int j = 0; j < 4; ++j) {
        int n = ty * 4 + j;
        float v = tile[tx][n];
        __nv_bfloat16 hv, lv;
        split_bf16(v, hv, lv);
        size_t o = (size_t)(n0 + n) * DM + m0 + tx;
        g_Eth[o] = hv;
        g_Etl[o] = lv;
    }
}

// ---------------------------------------------------------------------------
// Kernel 4: HMMA GEMM. 128x128 tile/CTA, grid 4x4x8 = 128 CTAs (1 wave).
// 512 threads = 16 warps (4x4), warp tile 32x32 (2 m16-tiles x 4 n8-tiles).
// K-chunks of 64 (16 stages: 2 phases x 8). Per stage: 4 tiles (Ah,Al,Bh,Bl)
// 128 rows x 128B, XOR-swizzled (chunk ^ row&7), cp.async double-buffered.
// Per k16: 4 ldmatrix.x4 (A) + 4 ldmatrix.x4 (B, two n-tiles each) + 24 MMA.
// ---------------------------------------------------------------------------
#define ROWB      128
#define TILE_B    (128 * ROWB)             // 16384
#define STAGE_B   (4 * TILE_B)             // 65536
#define GEMM_SMEM (2 * STAGE_B)            // 131072

#define MMA_BF16(c, a, b0, b1) \
    asm volatile("mma.sync.aligned.m16n8k16.row.col.f32.bf16.bf16.f32 " \
        "{%0,%1,%2,%3}, {%4,%5,%6,%7}, {%8,%9}, {%0,%1,%2,%3};" \
        : "+f"((c)[0]), "+f"((c)[1]), "+f"((c)[2]), "+f"((c)[3]) \
        : "r"((a)[0]), "r"((a)[1]), "r"((a)[2]), "r"((a)[3]), "r"(b0), "r"(b1))

#define LDSM_X4(r, addr) \
    asm volatile("ldmatrix.sync.aligned.m8n8.x4.shared.b16 {%0,%1,%2,%3}, [%4];" \
        : "=r"((r)[0]), "=r"((r)[1]), "=r"((r)[2]), "=r"((r)[3]) : "r"(addr))

#define CP_ASYNC16(dst, src) \
    asm volatile("cp.async.cg.shared.global [%0], [%1], 16;" :: "r"(dst), "l"(src))

struct StagePtrs { const __nv_bfloat16 *Ah, *Al, *Bh, *Bl; };

__device__ __forceinline__ StagePtrs stage_ptrs(int s, int b, int row0, int col0) {
    const int phase = s >> 3;
    const int kofs  = (s & 7) * 64;
    StagePtrs sp;
    if (phase == 0) {
        sp.Ah = g_Qh + ((size_t)b * SEQ + row0) * DM + kofs;
        sp.Al = g_Ql + ((size_t)b * SEQ + row0) * DM + kofs;
        sp.Bh = g_Kh + ((size_t)b * SEQ + col0) * DM + kofs;
        sp.Bl = g_Kl + ((size_t)b * SEQ + col0) * DM + kofs;
    } else {
        sp.Ah = g_Ph + ((size_t)b * SEQ + row0) * DM + kofs;
        sp.Al = g_Pl + ((size_t)b * SEQ + row0) * DM + kofs;
        sp.Bh = g_Eth + (size_t)col0 * DM + kofs;
        sp.Bl = g_Etl + (size_t)col0 * DM + kofs;
    }
    return sp;
}

__global__ __launch_bounds__(512, 1) void mma_gemm_kernel(float* __restrict__ out) {
    extern __shared__ char smem[];
    const uint32_t sb = smem_u32(smem);

    const int tid = threadIdx.x;
    const int wid = tid >> 5;
    const int lid = tid & 31;
    const int wm  = wid & 3;       // warp row (0..3) -> 32 rows
    const int wn  = wid >> 2;      // warp col (0..3) -> 32 cols
    const int b    = blockIdx.z;
    const int row0 = blockIdx.y * 128;
    const int col0 = blockIdx.x * 128;

    // cp.async mapping: thread -> row tid>>2, chunks (tid&3) and (tid&3)+4.
    const int l_row = tid >> 2;
    const int l_c0  = tid & 3;
    const uint32_t st0 = (uint32_t)(l_row * ROWB + ((l_c0 ^ (l_row & 7)) << 4));
    const uint32_t st1 = (uint32_t)(l_row * ROWB + (((l_c0 + 4) ^ (l_row & 7)) << 4));
    const size_t   go0 = (size_t)l_row * DM + l_c0 * 8;
    const size_t   go1 = go0 + 32;

    float acc[2][4][4];
#pragma unroll
    for (int mt = 0; mt < 2; ++mt)
#pragma unroll
        for (int nt = 0; nt < 4; ++nt)
#pragma unroll
            for (int r = 0; r < 4; ++r) acc[mt][nt][r] = 0.f;

    // ldmatrix lane rows (fixed per lane).
    const int a_row0 = wm * 32 + (lid & 15);          // + mt*16
    const int a_kh   = lid >> 4;                      // 0/1 -> +chunk
    const int g      = lid >> 3;
    const int b_row0 = wn * 32 + (g >> 1) * 8 + (lid & 7);  // + np*16
    const int b_kh   = g & 1;

    const int NCHUNK = 16;

    // Prologue: stage 0.
    {
        StagePtrs sp = stage_ptrs(0, b, row0, col0);
        uint32_t d = sb;
        CP_ASYNC16(d + st0,              sp.Ah + go0);
        CP_ASYNC16(d + st1,              sp.Ah + go1);
        CP_ASYNC16(d + TILE_B + st0,     sp.Al + go0);
        CP_ASYNC16(d + TILE_B + st1,     sp.Al + go1);
        CP_ASYNC16(d + 2 * TILE_B + st0, sp.Bh + go0);
        CP_ASYNC16(d + 2 * TILE_B + st1, sp.Bh + go1);
        CP_ASYNC16(d + 3 * TILE_B + st0, sp.Bl + go0);
        CP_ASYNC16(d + 3 * TILE_B + st1, sp.Bl + go1);
        asm volatile("cp.async.commit_group;");
    }

    for (int s = 0; s < NCHUNK; ++s) {
        if (s + 1 < NCHUNK) {
            StagePtrs sp = stage_ptrs(s + 1, b, row0, col0);
            uint32_t d = sb + ((s + 1) & 1) * STAGE_B;
            CP_ASYNC16(d + st0,              sp.Ah + go0);
            CP_ASYNC16(d + st1,              sp.Ah + go1);
            CP_ASYNC16(d + TILE_B + st0,     sp.Al + go0);
            CP_ASYNC16(d + TILE_B + st1,     sp.Al + go1);
            CP_ASYNC16(d + 2 * TILE_B + st0, sp.Bh + go0);
            CP_ASYNC16(d + 2 * TILE_B + st1, sp.Bh + go1);
            CP_ASYNC16(d + 3 * TILE_B + st0, sp.Bl + go0);
            CP_ASYNC16(d + 3 * TILE_B + st1, sp.Bl + go1);
            asm volatile("cp.async.commit_group;");
            asm volatile("cp.async.wait_group 1;");
        } else {
            asm volatile("cp.async.wait_group 0;");
        }
        __syncthreads();

        const uint32_t base = sb + (s & 1) * STAGE_B;
        const uint32_t tAh = base, tAl = base + TILE_B;
        const uint32_t tBh = base + 2 * TILE_B, tBl = base + 3 * TILE_B;

#pragma unroll
        for (int ks = 0; ks < 4; ++ks) {
            uint32_t ah[2][4], al[2][4], bh[2][4], bl[2][4];
#pragma unroll
            for (int mt = 0; mt < 2; ++mt) {
                const int row = a_row0 + mt * 16;
                const int kc  = 2 * ks + a_kh;
                const uint32_t off = (uint32_t)(row * ROWB + ((kc ^ (row & 7)) << 4));
                LDSM_X4(ah[mt], tAh + off);
                LDSM_X4(al[mt], tAl + off);
            }
#pragma unroll
            for (int np = 0; np < 2; ++np) {
                const int row = b_row0 + np * 16;
                const int kc  = 2 * ks + b_kh;
                const uint32_t off = (uint32_t)(row * ROWB + ((kc ^ (row & 7)) << 4));
                LDSM_X4(bh[np], tBh + off);
                LDSM_X4(bl[np], tBl + off);
            }
#pragma unroll
            for (int mt = 0; mt < 2; ++mt)
#pragma unroll
                for (int np = 0; np < 2; ++np)
#pragma unroll
                    for (int sub = 0; sub < 2; ++sub) {
                        const int nt = np * 2 + sub;
                        MMA_BF16(acc[mt][nt], ah[mt], bh[np][2 * sub], bh[np][2 * sub + 1]);
                        MMA_BF16(acc[mt][nt], ah[mt], bl[np][2 * sub], bl[np][2 * sub + 1]);
                        MMA_BF16(acc[mt][nt], al[mt], bh[np][2 * sub], bh[np][2 * sub + 1]);
                    }
        }
        __syncthreads();
    }

    // Epilogue: rows wm*32 + mt*16 + (lid>>2) + {0,8}; cols wn*32 + nt*8 + (lid&3)*2.
    float* ob = out + (size_t)b * SEQ * SEQ;
#pragma unroll
    for (int mt = 0; mt < 2; ++mt) {
#pragma unroll
        for (int nt = 0; nt < 4; ++nt) {
            const int rbase = row0 + wm * 32 + mt * 16 + (lid >> 2);
            const int c     = col0 + wn * 32 + nt * 8 + (lid & 3) * 2;
            *(float2*)(ob + (size_t)rbase * SEQ + c) =
                make_float2(acc[mt][nt][0], acc[mt][nt][1]);
            *(float2*)(ob + (size_t)(rbase + 8) * SEQ + c) =
                make_float2(acc[mt][nt][2], acc[mt][nt][3]);
        }
    }
}

// ---------------------------------------------------------------------------
extern "C" void kernel_launch(void* const* d_in, const int* in_sizes, int n_in,
                              void* d_out, int out_size) {
    const float* q = (const float*)d_in[0];
    const float* k = (const float*)d_in[1];
    const float* e = (const float*)d_in[2];
    float* out = (float*)d_out;
    (void)in_sizes; (void)n_in; (void)out_size;

    build_P_kernel<<<dim3(SEQ, BATCH), 256>>>(q);
    dec_k_kernel<<<NELEM / 8 / 256, 256>>>(k);
    dec_E_kernel<<<dim3(16, 16), 256>>>(e);

    cudaFuncSetAttribute(mma_gemm_kernel,
                         cudaFuncAttributeMaxDynamicSharedMemorySize, GEMM_SMEM);
    mma_gemm_kernel<<<dim3(4, 4, BATCH), 512, GEMM_SMEM>>>(out);
}